// round 4
// baseline (speedup 1.0000x reference)
#include <cuda_runtime.h>

// Problem constants
#define H    8
#define M    1024
#define D    64
#define B    8
#define L    2048
#define NTOK 16384     // B*L tokens per head
#define TOK  64        // tokens per block
#define CHUNK 128      // codes per smem chunk

// d_out packing (float32): z_q | vq_loss | indices | new_codebooks
#define ZQ_OFF   ((size_t)0)
#define LOSS_OFF ((size_t)8388608)
#define IDX_OFF  ((size_t)8388609)
#define CB_OFF   ((size_t)8519681)

typedef unsigned long long u64;

// Scratch (no allocations allowed -> __device__ globals). Zero at module load;
// re-zeroed at the TAIL of every kernel_launch so each call sees clean state.
__device__ float g_sums[H * M * D];
__device__ float g_counts[H * M];
__device__ float g_loss;

// ---------------------------------------------------------------------------
// packed f32x2 helpers (Blackwell FFMA2 path, only reachable via PTX)
// ---------------------------------------------------------------------------
__device__ __forceinline__ u64 ffma2(u64 a, u64 b, u64 c) {
    u64 d;
    asm("fma.rn.f32x2 %0, %1, %2, %3;" : "=l"(d) : "l"(a), "l"(b), "l"(c));
    return d;
}
__device__ __forceinline__ u64 pack2(float lo, float hi) {
    u64 r;
    asm("mov.b64 %0, {%1, %2};" : "=l"(r) : "f"(lo), "f"(hi));
    return r;
}
__device__ __forceinline__ float2 unpack2(u64 v) {
    float lo, hi;
    asm("mov.b64 {%0, %1}, %2;" : "=f"(lo), "=f"(hi) : "l"(v));
    return make_float2(lo, hi);
}

// ---------------------------------------------------------------------------
struct Smem {
    float zs[D][TOK];      // z tile, k-major: 16 KB (broadcast, conflict-free)
    float cs[D][CHUNK];    // codebook chunk, k-major, column-PERMUTED: 32 KB
                           // code c lives at column (c>>2 & 1)*64 + (c>>3)*4 + (c&3)
    float pb[2][16][4];    // per-(tx-half, ty, t) partial argmax value
    int   pi[2][16][4];    // and index
    int   sidx[TOK];
    float red[8];
};

// ---------------------------------------------------------------------------
__global__ void zero_kernel() {
    int i = blockIdx.x * 256 + threadIdx.x;
    if (i < H * M * D) g_sums[i] = 0.0f;
    if (i < H * M)     g_counts[i] = 0.0f;
    if (i == 0)        g_loss = 0.0f;
}

// ---------------------------------------------------------------------------
// Main kernel: register-blocked sim GEMM + argmax + fused epilogue.
// Block: 64 tokens x 1024 codes (8 chunks of 128). Thread: 4 tokens x 8 codes.
// 3 CTAs/SM (24 warps) for latency hiding; per warp-k: 16 FFMA2 (32 pipe-cyc)
// vs ~25 issue slots -> structurally FMA-bound.
// ---------------------------------------------------------------------------
__global__ __launch_bounds__(256, 3)
void vq_main(const float* __restrict__ z, const float* __restrict__ cb,
             float* __restrict__ out) {
    extern __shared__ char smem_raw[];
    Smem& s = *reinterpret_cast<Smem*>(smem_raw);

    const int tid  = threadIdx.x;
    const int wid  = tid >> 5;
    const int lane = tid & 31;
    const int h    = blockIdx.y;
    const int n0   = blockIdx.x * TOK;
    const int b    = n0 >> 11;          // n0 / L
    const int l0   = n0 & (L - 1);      // n0 % L (multiple of 64 -> aligned)

    // Warp footprint: 8 distinct tx x 4 distinct ty per warp.
    const int tx = (lane & 7) | ((wid & 1) << 3);   // 0..15, 8 codes each
    const int ty = (lane >> 3) | ((wid >> 1) << 2); // 0..15, 4 tokens each

    // ---- load z tile [64 k x 64 tok], coalesced float4 ----
    const size_t zbase = ((size_t)(b * 512 + h * 64)) * (size_t)L + (size_t)l0;
#pragma unroll
    for (int r = 0; r < 4; r++) {
        int f  = tid + 256 * r;         // float4 id, 1024 total
        int k  = f >> 4;
        int t4 = f & 15;
        float4 v = *(const float4*)(z + zbase + (size_t)k * L + (size_t)t4 * 4);
        *(float4*)&s.zs[k][t4 * 4] = v;
    }

    float best[4];
    int   bidx[4];
#pragma unroll
    for (int t = 0; t < 4; t++) { best[t] = -3.4e38f; bidx[t] = 0; }

    const float* cbh = cb + (size_t)h * M * D;

    for (int cc = 0; cc < M / CHUNK; cc++) {
        __syncthreads();   // protect cs from previous chunk's readers (covers zs load too)
        // ---- load codebook chunk transposed + column-permuted into cs[k][pcol] ----
        {
            int m    = tid & 127;                  // code row within chunk
            int kh   = tid >> 7;                   // k-half
            int pcol = (((m >> 2) & 1) << 6) | ((m >> 3) << 2) | (m & 3);
            const float* src = cbh + (size_t)(cc * CHUNK + m) * D + kh * 32;
#pragma unroll
            for (int q = 0; q < 8; q++) {
                float4 v = *(const float4*)(src + q * 4);
                int k0 = kh * 32 + q * 4;
                s.cs[k0 + 0][pcol] = v.x;
                s.cs[k0 + 1][pcol] = v.y;
                s.cs[k0 + 2][pcol] = v.z;
                s.cs[k0 + 3][pcol] = v.w;
            }
        }
        __syncthreads();

        u64 acc[4][4];
#pragma unroll
        for (int t = 0; t < 4; t++)
#pragma unroll
            for (int j = 0; j < 4; j++) acc[t][j] = 0ull;

#pragma unroll 4
        for (int k = 0; k < D; k++) {
            float4 za = *(const float4*)&s.zs[k][ty * 4];
            // codes tx*8+0..3 at column tx*4, codes tx*8+4..7 at column 64+tx*4
            ulonglong2 cA = *(const ulonglong2*)&s.cs[k][tx * 4];
            ulonglong2 cB = *(const ulonglong2*)&s.cs[k][64 + tx * 4];
            const u64 cp0 = cA.x, cp1 = cA.y, cp2 = cB.x, cp3 = cB.y;
            float zv[4] = {za.x, za.y, za.z, za.w};
#pragma unroll
            for (int t = 0; t < 4; t++) {
                u64 zd = pack2(zv[t], zv[t]);
                acc[t][0] = ffma2(zd, cp0, acc[t][0]);
                acc[t][1] = ffma2(zd, cp1, acc[t][1]);
                acc[t][2] = ffma2(zd, cp2, acc[t][2]);
                acc[t][3] = ffma2(zd, cp3, acc[t][3]);
            }
        }

        const int mbase = cc * CHUNK + tx * 8;
#pragma unroll
        for (int t = 0; t < 4; t++) {
#pragma unroll
            for (int j = 0; j < 4; j++) {
                float2 v = unpack2(acc[t][j]);
                if (v.x > best[t]) { best[t] = v.x; bidx[t] = mbase + 2 * j; }
                if (v.y > best[t]) { best[t] = v.y; bidx[t] = mbase + 2 * j + 1; }
            }
        }
    }

    // ---- argmax reduction: over the 8 tx-lanes within the warp ----
#pragma unroll
    for (int t = 0; t < 4; t++) {
#pragma unroll
        for (int off = 1; off < 8; off <<= 1) {
            float ob = __shfl_xor_sync(0xffffffffu, best[t], off);
            int   oi = __shfl_xor_sync(0xffffffffu, bidx[t], off);
            if (ob > best[t] || (ob == best[t] && oi < bidx[t])) {
                best[t] = ob; bidx[t] = oi;
            }
        }
    }
    if ((lane & 7) == 0) {
        int half = wid & 1;
#pragma unroll
        for (int t = 0; t < 4; t++) {
            s.pb[half][ty][t] = best[t];
            s.pi[half][ty][t] = bidx[t];
        }
    }
    __syncthreads();

    // ---- combine the two tx-halves; write indices + counts ----
    if (tid < TOK) {
        int tyy = tid >> 2, t = tid & 3;
        float b0 = s.pb[0][tyy][t], b1 = s.pb[1][tyy][t];
        int   i0 = s.pi[0][tyy][t], i1 = s.pi[1][tyy][t];
        int m = (b1 > b0 || (b1 == b0 && i1 < i0)) ? i1 : i0;
        s.sidx[tid] = m;
        out[IDX_OFF + ((size_t)b * H + (size_t)h) * (size_t)L + (size_t)(l0 + tid)] = (float)m;
        atomicAdd(&g_counts[h * M + m], 1.0f);
    }
    __syncthreads();

    // ---- epilogue: z_q, loss, segment sums ----
    float lsum = 0.0f;
#pragma unroll
    for (int i = 0; i < 16; i++) {
        int e = i * 256 + tid;          // 4096 elements: (k, tok)
        int k = e >> 6;
        int t = e & 63;
        int m = s.sidx[t];
        float c  = __ldg(cbh + (size_t)m * D + k);
        float zv = s.zs[k][t];
        size_t o = ((size_t)(b * 512 + h * 64 + k)) * (size_t)L + (size_t)(l0 + t);
        out[ZQ_OFF + o] = c;
        float dd = zv - c;
        lsum += dd * dd;
        atomicAdd(&g_sums[(h * M + m) * D + k], zv);
    }

    // block-reduce loss -> one atomic per block
#pragma unroll
    for (int o = 16; o > 0; o >>= 1)
        lsum += __shfl_xor_sync(0xffffffffu, lsum, o);
    if ((tid & 31) == 0) s.red[tid >> 5] = lsum;
    __syncthreads();
    if (tid == 0) {
        float tt = 0.0f;
#pragma unroll
        for (int w = 0; w < 8; w++) tt += s.red[w];
        atomicAdd(&g_loss, tt);
    }
}

// ---------------------------------------------------------------------------
// Update kernel: slerp + rms_norm codebook EMA (1 warp per code) + vq_loss.
// ---------------------------------------------------------------------------
__global__ void vq_update(const float* __restrict__ cb, float* __restrict__ out) {
    if (blockIdx.x == 0 && threadIdx.x == 0) {
        // vq_loss = codebook_loss + 0.25*commitment_loss = 1.25 * MSE
        out[LOSS_OFF] = 1.25f * g_loss * (1.0f / 8388608.0f);
    }

    const int code = blockIdx.x * 8 + (threadIdx.x >> 5);
    const int lane = threadIdx.x & 31;
    if (code >= H * M) return;

    const float* old = cb + (size_t)code * D;
    float o0 = old[lane];
    float o1 = old[lane + 32];
    float cnt = g_counts[code];
    float r0, r1;

    if (cnt > 0.0f) {
        float m0 = g_sums[code * D + lane] / cnt;
        float m1 = g_sums[code * D + lane + 32] / cnt;

        float dot = m0 * o0 + m1 * o1;
        float nl  = m0 * m0 + m1 * m1;
        float nh  = o0 * o0 + o1 * o1;
#pragma unroll
        for (int o = 16; o > 0; o >>= 1) {
            dot += __shfl_xor_sync(0xffffffffu, dot, o);
            nl  += __shfl_xor_sync(0xffffffffu, nl,  o);
            nh  += __shfl_xor_sync(0xffffffffu, nh,  o);
        }
        float cosv = dot / fmaxf(sqrtf(nl) * sqrtf(nh), 1e-8f);
        cosv = fminf(fmaxf(cosv, (float)(-1.0 + 1e-7)), (float)(1.0 - 1e-7));
        float omega = acosf(cosv);
        float so = sinf(omega);
        float wl = sinf(0.01f * omega);   // (1 - decay) * omega
        float wh = sinf(0.99f * omega);   // decay * omega
        r0 = (m0 * wl + o0 * wh) / so;
        r1 = (m1 * wl + o1 * wh) / so;

        float ss = r0 * r0 + r1 * r1;
#pragma unroll
        for (int o = 16; o > 0; o >>= 1)
            ss += __shfl_xor_sync(0xffffffffu, ss, o);
        float inv = 1.0f / sqrtf(ss * (1.0f / 64.0f) + 1.1920929e-07f);
        r0 *= inv;
        r1 *= inv;
    } else {
        r0 = o0;
        r1 = o1;
    }

    out[CB_OFF + (size_t)code * D + lane]      = r0;
    out[CB_OFF + (size_t)code * D + lane + 32] = r1;
}

// ---------------------------------------------------------------------------
extern "C" void kernel_launch(void* const* d_in, const int* in_sizes, int n_in,
                              void* d_out, int out_size) {
    const float* z  = (const float*)d_in[0];   // [8, 512, 2048]
    const float* cb = (const float*)d_in[1];   // [8, 1024, 64]
    float* out = (float*)d_out;

    cudaFuncSetAttribute(vq_main, cudaFuncAttributeMaxDynamicSharedMemorySize,
                         (int)sizeof(Smem));

    dim3 grid(NTOK / TOK, H);
    vq_main<<<grid, 256, sizeof(Smem)>>>(z, cb, out);

    vq_update<<<H * M / 8, 256>>>(cb, out);

    // Reset scratch for the NEXT invocation (initial state is zero at load).
    zero_kernel<<<(H * M * D + 255) / 256, 256>>>();
}

// round 5
// speedup vs baseline: 1.2108x; 1.2108x over previous
#include <cuda_runtime.h>

// Problem constants
#define H    8
#define M    1024
#define D    64
#define B    8
#define L    2048
#define NTOK 16384     // B*L tokens per head
#define TOK  128       // tokens per block
#define CHUNK 128      // codes per smem chunk

// d_out packing (float32): z_q | vq_loss | indices | new_codebooks
#define ZQ_OFF   ((size_t)0)
#define LOSS_OFF ((size_t)8388608)
#define IDX_OFF  ((size_t)8388609)
#define CB_OFF   ((size_t)8519681)

typedef unsigned long long u64;

// Scratch (no allocations allowed -> __device__ globals). Zero at module load;
// re-zeroed at the TAIL of every kernel_launch so each call sees clean state.
__device__ float g_sums[H * M * D];
__device__ float g_counts[H * M];
__device__ float g_loss;

// ---------------------------------------------------------------------------
// packed f32x2 helpers (Blackwell FFMA2 path, only reachable via PTX)
// ---------------------------------------------------------------------------
__device__ __forceinline__ u64 ffma2(u64 a, u64 b, u64 c) {
    u64 d;
    asm("fma.rn.f32x2 %0, %1, %2, %3;" : "=l"(d) : "l"(a), "l"(b), "l"(c));
    return d;
}
__device__ __forceinline__ u64 pack2(float lo, float hi) {
    u64 r;
    asm("mov.b64 %0, {%1, %2};" : "=l"(r) : "f"(lo), "f"(hi));
    return r;
}
__device__ __forceinline__ float2 unpack2(u64 v) {
    float lo, hi;
    asm("mov.b64 {%0, %1}, %2;" : "=f"(lo), "=f"(hi) : "l"(v));
    return make_float2(lo, hi);
}

// ---------------------------------------------------------------------------
struct Smem {
    float zs[D][TOK];         // z tile, k-major: 32 KB
    float cs[2][D][CHUNK];    // DOUBLE-BUFFERED codebook chunk, k-major: 64 KB
    int   sidx[TOK];
    float red[8];
};

// ---------------------------------------------------------------------------
__global__ void zero_kernel() {
    int i = blockIdx.x * 256 + threadIdx.x;
    if (i < H * M * D) g_sums[i] = 0.0f;
    if (i < H * M)     g_counts[i] = 0.0f;
    if (i == 0)        g_loss = 0.0f;
}

// ---------------------------------------------------------------------------
// Chunk loader: transpose codebook chunk cc into cs[buf][k][m].
// Stores are conflict-free (fixed k row, consecutive m across lanes).
// ---------------------------------------------------------------------------
__device__ __forceinline__ void load_chunk(Smem& s, const float* __restrict__ cbh,
                                           int cc, int buf, int tid) {
    int m  = tid & 127;                 // code row within chunk
    int kh = tid >> 7;                  // k-half
    const float* src = cbh + (size_t)(cc * CHUNK + m) * D + kh * 32;
#pragma unroll
    for (int q = 0; q < 8; q++) {
        float4 v = *(const float4*)(src + q * 4);
        int k0 = kh * 32 + q * 4;
        s.cs[buf][k0 + 0][m] = v.x;
        s.cs[buf][k0 + 1][m] = v.y;
        s.cs[buf][k0 + 2][m] = v.z;
        s.cs[buf][k0 + 3][m] = v.w;
    }
}

// ---------------------------------------------------------------------------
// Main kernel: register-blocked sim GEMM + argmax + fused epilogue.
// Block: 128 tokens x 1024 codes (8 chunks of 128). Thread: 8 tokens x 8 codes.
// Codebook chunks double-buffered: one barrier per chunk; a warp's load stall
// on chunk cc+1 overlaps other warps' FMA work on chunk cc.
// ---------------------------------------------------------------------------
__global__ __launch_bounds__(256, 2)
void vq_main(const float* __restrict__ z, const float* __restrict__ cb,
             float* __restrict__ out) {
    extern __shared__ char smem_raw[];
    Smem& s = *reinterpret_cast<Smem*>(smem_raw);

    const int tid = threadIdx.x;
    const int h   = blockIdx.y;
    const int n0  = blockIdx.x * TOK;
    const int b   = n0 >> 11;           // n0 / L
    const int l0  = n0 & (L - 1);       // n0 % L (multiple of 128 -> aligned)
    const int tx  = tid & 15;           // code group 0..15
    const int ty  = tid >> 4;           // token group 0..15

    // ---- load z tile [64 k x 128 tok], coalesced float4 ----
    const size_t zbase = ((size_t)(b * 512 + h * 64)) * (size_t)L + (size_t)l0;
#pragma unroll
    for (int r = 0; r < 8; r++) {
        int f  = tid + 256 * r;         // float4 id, 2048 total
        int k  = f >> 5;
        int t4 = f & 31;
        float4 v = *(const float4*)(z + zbase + (size_t)k * L + (size_t)t4 * 4);
        *(float4*)&s.zs[k][t4 * 4] = v;
    }

    float best[8];
    int   bidx[8];
#pragma unroll
    for (int t = 0; t < 8; t++) { best[t] = -3.4e38f; bidx[t] = 0; }

    const float* cbh = cb + (size_t)h * M * D;

    // prologue: chunk 0 into buffer 0
    load_chunk(s, cbh, 0, 0, tid);
    __syncthreads();

    for (int cc = 0; cc < M / CHUNK; cc++) {
        const int p = cc & 1;
        // Prefetch next chunk into the other buffer (was last read 2 phases ago;
        // the barrier at the end of the previous iteration makes this safe).
        if (cc + 1 < M / CHUNK) load_chunk(s, cbh, cc + 1, p ^ 1, tid);

        u64 acc[8][4];
#pragma unroll
        for (int t = 0; t < 8; t++)
#pragma unroll
            for (int j = 0; j < 4; j++) acc[t][j] = 0ull;

#pragma unroll 4
        for (int k = 0; k < D; k++) {
            float4 za = *(const float4*)&s.zs[k][ty * 8];
            float4 zb = *(const float4*)&s.zs[k][ty * 8 + 4];
            ulonglong2 c01 = *(const ulonglong2*)&s.cs[p][k][tx * 8];
            ulonglong2 c23 = *(const ulonglong2*)&s.cs[p][k][tx * 8 + 4];
            const u64 cp0 = c01.x, cp1 = c01.y, cp2 = c23.x, cp3 = c23.y;
            float zv[8] = {za.x, za.y, za.z, za.w, zb.x, zb.y, zb.z, zb.w};
#pragma unroll
            for (int t = 0; t < 8; t++) {
                u64 zd = pack2(zv[t], zv[t]);
                acc[t][0] = ffma2(zd, cp0, acc[t][0]);
                acc[t][1] = ffma2(zd, cp1, acc[t][1]);
                acc[t][2] = ffma2(zd, cp2, acc[t][2]);
                acc[t][3] = ffma2(zd, cp3, acc[t][3]);
            }
        }

        const int mbase = cc * CHUNK + tx * 8;
#pragma unroll
        for (int t = 0; t < 8; t++) {
#pragma unroll
            for (int j = 0; j < 4; j++) {
                float2 v = unpack2(acc[t][j]);
                if (v.x > best[t]) { best[t] = v.x; bidx[t] = mbase + 2 * j; }
                if (v.y > best[t]) { best[t] = v.y; bidx[t] = mbase + 2 * j + 1; }
            }
        }

        __syncthreads();   // publish next buffer; release current buffer
    }

    // ---- argmax reduction across the 16 code-lanes (tx); first-index tie-break ----
#pragma unroll
    for (int t = 0; t < 8; t++) {
#pragma unroll
        for (int off = 1; off < 16; off <<= 1) {
            float ob = __shfl_xor_sync(0xffffffffu, best[t], off);
            int   oi = __shfl_xor_sync(0xffffffffu, bidx[t], off);
            if (ob > best[t] || (ob == best[t] && oi < bidx[t])) {
                best[t] = ob; bidx[t] = oi;
            }
        }
        if (tx == 0) s.sidx[ty * 8 + t] = bidx[t];
    }
    __syncthreads();

    // ---- epilogue: indices, counts, z_q, loss, segment sums ----
    if (tid < TOK) {
        int m = s.sidx[tid];
        out[IDX_OFF + ((size_t)b * H + (size_t)h) * (size_t)L + (size_t)(l0 + tid)] = (float)m;
        atomicAdd(&g_counts[h * M + m], 1.0f);
    }

    float lsum = 0.0f;
#pragma unroll
    for (int i = 0; i < 32; i++) {
        int e = i * 256 + tid;          // 8192 elements: (k, tok)
        int k = e >> 7;
        int t = e & 127;
        int m = s.sidx[t];
        float c  = __ldg(cbh + (size_t)m * D + k);
        float zv = s.zs[k][t];
        size_t o = ((size_t)(b * 512 + h * 64 + k)) * (size_t)L + (size_t)(l0 + t);
        out[ZQ_OFF + o] = c;
        float dd = zv - c;
        lsum += dd * dd;
        atomicAdd(&g_sums[(h * M + m) * D + k], zv);
    }

    // block-reduce loss -> one atomic per block
#pragma unroll
    for (int o = 16; o > 0; o >>= 1)
        lsum += __shfl_xor_sync(0xffffffffu, lsum, o);
    if ((tid & 31) == 0) s.red[tid >> 5] = lsum;
    __syncthreads();
    if (tid == 0) {
        float tt = 0.0f;
#pragma unroll
        for (int w = 0; w < 8; w++) tt += s.red[w];
        atomicAdd(&g_loss, tt);
    }
}

// ---------------------------------------------------------------------------
// Update kernel: slerp + rms_norm codebook EMA (1 warp per code) + vq_loss.
// ---------------------------------------------------------------------------
__global__ void vq_update(const float* __restrict__ cb, float* __restrict__ out) {
    if (blockIdx.x == 0 && threadIdx.x == 0) {
        // vq_loss = codebook_loss + 0.25*commitment_loss = 1.25 * MSE
        out[LOSS_OFF] = 1.25f * g_loss * (1.0f / 8388608.0f);
    }

    const int code = blockIdx.x * 8 + (threadIdx.x >> 5);
    const int lane = threadIdx.x & 31;
    if (code >= H * M) return;

    const float* old = cb + (size_t)code * D;
    float o0 = old[lane];
    float o1 = old[lane + 32];
    float cnt = g_counts[code];
    float r0, r1;

    if (cnt > 0.0f) {
        float m0 = g_sums[code * D + lane] / cnt;
        float m1 = g_sums[code * D + lane + 32] / cnt;

        float dot = m0 * o0 + m1 * o1;
        float nl  = m0 * m0 + m1 * m1;
        float nh  = o0 * o0 + o1 * o1;
#pragma unroll
        for (int o = 16; o > 0; o >>= 1) {
            dot += __shfl_xor_sync(0xffffffffu, dot, o);
            nl  += __shfl_xor_sync(0xffffffffu, nl,  o);
            nh  += __shfl_xor_sync(0xffffffffu, nh,  o);
        }
        float cosv = dot / fmaxf(sqrtf(nl) * sqrtf(nh), 1e-8f);
        cosv = fminf(fmaxf(cosv, (float)(-1.0 + 1e-7)), (float)(1.0 - 1e-7));
        float omega = acosf(cosv);
        float so = sinf(omega);
        float wl = sinf(0.01f * omega);   // (1 - decay) * omega
        float wh = sinf(0.99f * omega);   // decay * omega
        r0 = (m0 * wl + o0 * wh) / so;
        r1 = (m1 * wl + o1 * wh) / so;

        float ss = r0 * r0 + r1 * r1;
#pragma unroll
        for (int o = 16; o > 0; o >>= 1)
            ss += __shfl_xor_sync(0xffffffffu, ss, o);
        float inv = 1.0f / sqrtf(ss * (1.0f / 64.0f) + 1.1920929e-07f);
        r0 *= inv;
        r1 *= inv;
    } else {
        r0 = o0;
        r1 = o1;
    }

    out[CB_OFF + (size_t)code * D + lane]      = r0;
    out[CB_OFF + (size_t)code * D + lane + 32] = r1;
}

// ---------------------------------------------------------------------------
extern "C" void kernel_launch(void* const* d_in, const int* in_sizes, int n_in,
                              void* d_out, int out_size) {
    const float* z  = (const float*)d_in[0];   // [8, 512, 2048]
    const float* cb = (const float*)d_in[1];   // [8, 1024, 64]
    float* out = (float*)d_out;

    cudaFuncSetAttribute(vq_main, cudaFuncAttributeMaxDynamicSharedMemorySize,
                         (int)sizeof(Smem));

    dim3 grid(NTOK / TOK, H);
    vq_main<<<grid, 256, sizeof(Smem)>>>(z, cb, out);

    vq_update<<<H * M / 8, 256>>>(cb, out);

    // Reset scratch for the NEXT invocation (initial state is zero at load).
    zero_kernel<<<(H * M * D + 255) / 256, 256>>>();
}

// round 11
// speedup vs baseline: 1.3597x; 1.1230x over previous
#include <cuda_runtime.h>
#include <cuda_fp16.h>
#include <cstdint>

// Problem constants
#define H    8
#define M    1024
#define D    64
#define B    8
#define L    2048
#define NTOK 16384
#define TOKC 128       // tokens per CTA
#define GN   128       // codes per group
#define NG   8         // groups
#define KP   72        // padded row length (halves) -> 144B rows, ldmatrix conflict-free

// d_out packing (float32): z_q | vq_loss | indices | new_codebooks
#define ZQ_OFF   ((size_t)0)
#define LOSS_OFF ((size_t)8388608)
#define IDX_OFF  ((size_t)8388609)
#define CB_OFF   ((size_t)8519681)

typedef unsigned int u32;

// Scratch (no allocations allowed -> __device__ globals). Zero at module load;
// re-zeroed at the TAIL of every kernel_launch.
__device__ float g_sums[H * M * D];
__device__ float g_counts[H * M];
__device__ float g_loss;

// ---------------------------------------------------------------------------
struct Smem {
    __half A[2][TOKC][KP];    // z tile hi/lo:      36864 B
    __half Bt[2][GN][KP];     // B group hi/lo:     36864 B
    float cv1[NG * TOKC];     // per-group top-1 value
    int   ci1[NG * TOKC];
    float cv2[NG * TOKC];     // per-group top-2 value
    int   ci2[NG * TOKC];
    int   sidx[TOKC];
    float red[8];
};

__device__ __forceinline__ u32 smem_u32(const void* p) {
    u32 a;
    asm("{ .reg .u64 t; cvta.to.shared.u64 t, %1; cvt.u32.u64 %0, t; }" : "=r"(a) : "l"(p));
    return a;
}

#define LDSM4(r0, r1, r2, r3, addr) \
    asm volatile("ldmatrix.sync.aligned.m8n8.x4.shared.b16 {%0,%1,%2,%3}, [%4];" \
        : "=r"(r0), "=r"(r1), "=r"(r2), "=r"(r3) : "r"(addr))
#define LDSM2(r0, r1, addr) \
    asm volatile("ldmatrix.sync.aligned.m8n8.x2.shared.b16 {%0,%1}, [%2];" \
        : "=r"(r0), "=r"(r1) : "r"(addr))
#define MMA16816(c0, c1, c2, c3, a0, a1, a2, a3, b0, b1) \
    asm volatile("mma.sync.aligned.m16n8k16.row.col.f32.f16.f16.f32 " \
        "{%0,%1,%2,%3},{%4,%5,%6,%7},{%8,%9},{%0,%1,%2,%3};" \
        : "+f"(c0), "+f"(c1), "+f"(c2), "+f"(c3) \
        : "r"(a0), "r"(a1), "r"(a2), "r"(a3), "r"(b0), "r"(b1))

__device__ __forceinline__ void split_h(float v, __half& hi, __half& lo) {
    hi = __float2half_rn(v);
    lo = __float2half_rn(v - __half2float(hi));
}
__device__ __forceinline__ bool better(float v, int i, float bv, int bi) {
    return v > bv || (v == bv && i < bi);
}

// ---------------------------------------------------------------------------
__global__ void zero_kernel() {
    int i = blockIdx.x * 256 + threadIdx.x;
    if (i < H * M * D) g_sums[i] = 0.0f;
    if (i < H * M)     g_counts[i] = 0.0f;
    if (i == 0)        g_loss = 0.0f;
}

// ---------------------------------------------------------------------------
// Main kernel: fp16 HMMA sim GEMM (3-pass hi/lo) + per-group top-2 + fp32
// re-rank + fused epilogue. Block: 128 tokens x 1024 codes; warp: 16 tok x 128
// codes per group; A fragments register-resident across all groups.
// ---------------------------------------------------------------------------
__global__ __launch_bounds__(256, 2)
void vq_main(const float* __restrict__ z, const float* __restrict__ cb,
             float* __restrict__ out) {
    extern __shared__ char smraw[];
    Smem& s = *reinterpret_cast<Smem*>(smraw);

    const int tid = threadIdx.x, wid = tid >> 5, lane = tid & 31;
    const int h = blockIdx.y;
    const int n0 = blockIdx.x * TOKC;
    const int b = n0 >> 11, l0 = n0 & (L - 1);
    const float* cbh = cb + (size_t)h * M * D;

    // ---- A tiles: z [64 k x 128 tok] -> fp16 hi/lo, rows = tokens ----
    const size_t zbase = ((size_t)(b * 512 + h * 64)) * (size_t)L + (size_t)l0;
#pragma unroll
    for (int r = 0; r < 8; r++) {
        int f  = tid + 256 * r;          // 2048 float4
        int k  = f >> 5;
        int t4 = (f & 31) * 4;
        float4 v = *(const float4*)(z + zbase + (size_t)k * L + (size_t)t4);
        float vv[4] = {v.x, v.y, v.z, v.w};
#pragma unroll
        for (int j = 0; j < 4; j++) {
            __half hi, lo;
            split_h(vv[j], hi, lo);
            s.A[0][t4 + j][k] = hi;
            s.A[1][t4 + j][k] = lo;
        }
    }
    __syncthreads();

    // ---- load A fragments (m16k16 x 4 ktiles x 2 halves) into registers ----
    const int tok0 = wid * 16;
    const int ar   = lane & 15;          // row within m16 tile
    const int ac8  = (lane >> 4) << 3;   // k-offset 0 or 8
    u32 af[2][4][4];
#pragma unroll
    for (int hh = 0; hh < 2; hh++)
#pragma unroll
        for (int kt = 0; kt < 4; kt++) {
            u32 addr = smem_u32(&s.A[hh][tok0 + ar][kt * 16 + ac8]);
            LDSM4(af[hh][kt][0], af[hh][kt][1], af[hh][kt][2], af[hh][kt][3], addr);
        }

    // B ldmatrix address lanes (x2): row = code within ntile, col8 select
    const int bn  = lane & 7;
    const int bc8 = ((lane >> 3) & 1) << 3;

    for (int g = 0; g < NG; g++) {
        __syncthreads();   // all warps done reading Bt of previous group
        // ---- load + split B group g: 128 codes x 64 k ----
        {
            int n  = tid >> 1;
            int kh = (tid & 1) * 32;
            const float* src = cbh + (size_t)(g * GN + n) * D + kh;
#pragma unroll
            for (int q = 0; q < 8; q++) {
                float4 v = *(const float4*)(src + q * 4);
                __half h0, l0h, h1, l1, h2, l2, h3, l3;
                split_h(v.x, h0, l0h); split_h(v.y, h1, l1);
                split_h(v.z, h2, l2);  split_h(v.w, h3, l3);
                int k0 = kh + q * 4;
                *(__half2*)&s.Bt[0][n][k0]     = __halves2half2(h0, h1);
                *(__half2*)&s.Bt[0][n][k0 + 2] = __halves2half2(h2, h3);
                *(__half2*)&s.Bt[1][n][k0]     = __halves2half2(l0h, l1);
                *(__half2*)&s.Bt[1][n][k0 + 2] = __halves2half2(l2, l3);
            }
        }
        __syncthreads();

        // ---- MMA over 16 n-tiles; per-thread top-2 for its 2 token rows ----
        float v1a = -3.4e38f, v2a = -3.4e38f, v1b = -3.4e38f, v2b = -3.4e38f;
        int   i1a = 0, i2a = 0, i1b = 0, i2b = 0;
#pragma unroll
        for (int nt = 0; nt < 16; nt++) {
            float c0 = 0.f, c1 = 0.f, c2 = 0.f, c3 = 0.f;
#pragma unroll
            for (int kt = 0; kt < 4; kt++) {
                u32 bh0, bh1, bl0, bl1;
                LDSM2(bh0, bh1, smem_u32(&s.Bt[0][nt * 8 + bn][kt * 16 + bc8]));
                LDSM2(bl0, bl1, smem_u32(&s.Bt[1][nt * 8 + bn][kt * 16 + bc8]));
                MMA16816(c0, c1, c2, c3, af[0][kt][0], af[0][kt][1], af[0][kt][2], af[0][kt][3], bh0, bh1);
                MMA16816(c0, c1, c2, c3, af[0][kt][0], af[0][kt][1], af[0][kt][2], af[0][kt][3], bl0, bl1);
                MMA16816(c0, c1, c2, c3, af[1][kt][0], af[1][kt][1], af[1][kt][2], af[1][kt][3], bh0, bh1);
            }
            int code0 = g * GN + nt * 8 + ((lane & 3) << 1);
            // token A (row lane>>2)
            if (better(c0, code0, v1a, i1a)) { v2a = v1a; i2a = i1a; v1a = c0; i1a = code0; }
            else if (better(c0, code0, v2a, i2a)) { v2a = c0; i2a = code0; }
            if (better(c1, code0 + 1, v1a, i1a)) { v2a = v1a; i2a = i1a; v1a = c1; i1a = code0 + 1; }
            else if (better(c1, code0 + 1, v2a, i2a)) { v2a = c1; i2a = code0 + 1; }
            // token B (row lane>>2 + 8)
            if (better(c2, code0, v1b, i1b)) { v2b = v1b; i2b = i1b; v1b = c2; i1b = code0; }
            else if (better(c2, code0, v2b, i2b)) { v2b = c2; i2b = code0; }
            if (better(c3, code0 + 1, v1b, i1b)) { v2b = v1b; i2b = i1b; v1b = c3; i1b = code0 + 1; }
            else if (better(c3, code0 + 1, v2b, i2b)) { v2b = c3; i2b = code0 + 1; }
        }

        // ---- merge top-2 across the 4 lanes of the quad (same token rows) ----
#pragma unroll
        for (int off = 1; off < 4; off <<= 1) {
            float w1 = __shfl_xor_sync(0xffffffffu, v1a, off);
            int   j1 = __shfl_xor_sync(0xffffffffu, i1a, off);
            float w2 = __shfl_xor_sync(0xffffffffu, v2a, off);
            int   j2 = __shfl_xor_sync(0xffffffffu, i2a, off);
            if (better(w1, j1, v1a, i1a)) {
                if (better(v1a, i1a, w2, j2)) { v2a = v1a; i2a = i1a; }
                else                          { v2a = w2;  i2a = j2;  }
                v1a = w1; i1a = j1;
            } else if (better(w1, j1, v2a, i2a)) { v2a = w1; i2a = j1; }

            w1 = __shfl_xor_sync(0xffffffffu, v1b, off);
            j1 = __shfl_xor_sync(0xffffffffu, i1b, off);
            w2 = __shfl_xor_sync(0xffffffffu, v2b, off);
            j2 = __shfl_xor_sync(0xffffffffu, i2b, off);
            if (better(w1, j1, v1b, i1b)) {
                if (better(v1b, i1b, w2, j2)) { v2b = v1b; i2b = i1b; }
                else                          { v2b = w2;  i2b = j2;  }
                v1b = w1; i1b = j1;
            } else if (better(w1, j1, v2b, i2b)) { v2b = w1; i2b = j1; }
        }
        if ((lane & 3) == 0) {
            int tokA = tok0 + (lane >> 2);
            s.cv1[g * TOKC + tokA] = v1a;  s.ci1[g * TOKC + tokA] = i1a;
            s.cv2[g * TOKC + tokA] = v2a;  s.ci2[g * TOKC + tokA] = i2a;
            int tokB = tokA + 8;
            s.cv1[g * TOKC + tokB] = v1b;  s.ci1[g * TOKC + tokB] = i1b;
            s.cv2[g * TOKC + tokB] = v2b;  s.ci2[g * TOKC + tokB] = i2b;
        }
    }
    __syncthreads();

    // ---- fp32 re-rank of candidates within margin of fp16 max ----
    if (tid < TOKC) {
        const int t = tid;
        float gmax = -3.4e38f;
#pragma unroll
        for (int g = 0; g < NG; g++)
            gmax = fmaxf(gmax, s.cv1[g * TOKC + t]);
        const float thr = gmax - 0.01f;   // margin >> fp16 3-pass error (~1e-5)
        int cidx[16];
        int cnt = 0;
#pragma unroll
        for (int g = 0; g < NG; g++) {
            if (s.cv1[g * TOKC + t] >= thr) cidx[cnt++] = s.ci1[g * TOKC + t];
            if (s.cv2[g * TOKC + t] >= thr) cidx[cnt++] = s.ci2[g * TOKC + t];
        }
        int m;
        if (cnt == 1) {
            m = cidx[0];
        } else {
            float bestv = -3.4e38f;
            m = 1 << 30;
            for (int j = 0; j < cnt; j++) {
                int idx = cidx[j];
                const float* crow = cbh + (size_t)idx * D;
                float dot = 0.0f;
#pragma unroll
                for (int k = 0; k < D; k++) {
                    float zv = __half2float(s.A[0][t][k]) + __half2float(s.A[1][t][k]);
                    dot += zv * __ldg(crow + k);
                }
                if (dot > bestv || (dot == bestv && idx < m)) { bestv = dot; m = idx; }
            }
        }
        s.sidx[t] = m;
        out[IDX_OFF + ((size_t)b * H + (size_t)h) * (size_t)L + (size_t)(l0 + t)] = (float)m;
        atomicAdd(&g_counts[h * M + m], 1.0f);
    }
    __syncthreads();

    // ---- epilogue: z_q, loss, segment sums (z = hi + lo, 2e-7 rel err) ----
    float lsum = 0.0f;
#pragma unroll
    for (int i = 0; i < 32; i++) {
        int e = i * 256 + tid;           // 8192 elements (k, tok)
        int k = e >> 7;
        int t = e & 127;
        int mm = s.sidx[t];
        float zv = __half2float(s.A[0][t][k]) + __half2float(s.A[1][t][k]);
        float c = __ldg(cbh + (size_t)mm * D + k);
        size_t o = ((size_t)(b * 512 + h * 64 + k)) * (size_t)L + (size_t)(l0 + t);
        out[ZQ_OFF + o] = c;
        float dd = zv - c;
        lsum += dd * dd;
        atomicAdd(&g_sums[(h * M + mm) * D + k], zv);
    }
#pragma unroll
    for (int o = 16; o > 0; o >>= 1)
        lsum += __shfl_xor_sync(0xffffffffu, lsum, o);
    if (lane == 0) s.red[wid] = lsum;
    __syncthreads();
    if (tid == 0) {
        float tt = 0.0f;
#pragma unroll
        for (int w = 0; w < 8; w++) tt += s.red[w];
        atomicAdd(&g_loss, tt);
    }
}

// ---------------------------------------------------------------------------
// Update kernel: slerp + rms_norm codebook EMA (1 warp per code) + vq_loss.
// ---------------------------------------------------------------------------
__global__ void vq_update(const float* __restrict__ cb, float* __restrict__ out) {
    if (blockIdx.x == 0 && threadIdx.x == 0)
        out[LOSS_OFF] = 1.25f * g_loss * (1.0f / 8388608.0f);

    const int code = blockIdx.x * 8 + (threadIdx.x >> 5);
    const int lane = threadIdx.x & 31;
    if (code >= H * M) return;

    const float* old = cb + (size_t)code * D;
    float o0 = old[lane];
    float o1 = old[lane + 32];
    float cnt = g_counts[code];
    float r0, r1;

    if (cnt > 0.0f) {
        float m0 = g_sums[code * D + lane] / cnt;
        float m1 = g_sums[code * D + lane + 32] / cnt;

        float dot = m0 * o0 + m1 * o1;
        float nl  = m0 * m0 + m1 * m1;
        float nh  = o0 * o0 + o1 * o1;
#pragma unroll
        for (int o = 16; o > 0; o >>= 1) {
            dot += __shfl_xor_sync(0xffffffffu, dot, o);
            nl  += __shfl_xor_sync(0xffffffffu, nl,  o);
            nh  += __shfl_xor_sync(0xffffffffu, nh,  o);
        }
        float cosv = dot / fmaxf(sqrtf(nl) * sqrtf(nh), 1e-8f);
        cosv = fminf(fmaxf(cosv, (float)(-1.0 + 1e-7)), (float)(1.0 - 1e-7));
        float omega = acosf(cosv);
        float so = sinf(omega);
        float wl = sinf(0.01f * omega);
        float wh = sinf(0.99f * omega);
        r0 = (m0 * wl + o0 * wh) / so;
        r1 = (m1 * wl + o1 * wh) / so;

        float ss = r0 * r0 + r1 * r1;
#pragma unroll
        for (int o = 16; o > 0; o >>= 1)
            ss += __shfl_xor_sync(0xffffffffu, ss, o);
        float inv = 1.0f / sqrtf(ss * (1.0f / 64.0f) + 1.1920929e-07f);
        r0 *= inv;
        r1 *= inv;
    } else {
        r0 = o0;
        r1 = o1;
    }

    out[CB_OFF + (size_t)code * D + lane]      = r0;
    out[CB_OFF + (size_t)code * D + lane + 32] = r1;
}

// ---------------------------------------------------------------------------
extern "C" void kernel_launch(void* const* d_in, const int* in_sizes, int n_in,
                              void* d_out, int out_size) {
    const float* z  = (const float*)d_in[0];   // [8, 512, 2048]
    const float* cb = (const float*)d_in[1];   // [8, 1024, 64]
    float* out = (float*)d_out;

    cudaFuncSetAttribute(vq_main, cudaFuncAttributeMaxDynamicSharedMemorySize,
                         (int)sizeof(Smem));

    dim3 grid(NTOK / TOKC, H);
    vq_main<<<grid, 256, sizeof(Smem)>>>(z, cb, out);

    vq_update<<<H * M / 8, 256>>>(cb, out);

    // Reset scratch for the NEXT invocation (initial state is zero at load).
    zero_kernel<<<(H * M * D + 255) / 256, 256>>>();
}